// round 4
// baseline (speedup 1.0000x reference)
#include <cuda_runtime.h>
#include <math.h>

#define NN 50000
#define EE 800000
#define ETOT (EE + NN)
#define DIM 128
#define HH 4
#define CC 32
#define NEG_SLOPE 0.2f

// ---------------- device scratch (no allocations allowed) ----------------
__device__ int    g_count[NN];
__device__ int    g_rowptr[NN + 1];
__device__ int    g_cursor[NN];
__device__ int    g_colidx[ETOT];
__device__ float  g_h[NN * DIM];      // activated layer input (layers 2,3)
__device__ float  g_hw[NN * DIM];     // transformed features of current layer
__device__ float  g_asrc[NN * HH];
__device__ float  g_adst[NN * HH];
__device__ float2 g_Wp[(DIM / 2) * DIM];   // K-pair packed weights (reused per layer)

// ---------------- CSR build ----------------
__global__ void k_init_count() {
    int i = blockIdx.x * blockDim.x + threadIdx.x;
    if (i < NN) g_count[i] = 1;   // self loop pre-counted
}

__global__ void k_count(const int* __restrict__ ei) {
    int e = blockIdx.x * blockDim.x + threadIdx.x;
    if (e < EE) atomicAdd(&g_count[ei[EE + e]], 1);
}

// single-block shuffle-based exclusive scan (N=50000)
__global__ void k_scan() {
    __shared__ int wsum[32];
    __shared__ int carry_s;
    int lane = threadIdx.x & 31;
    int wid  = threadIdx.x >> 5;
    if (threadIdx.x == 0) carry_s = 0;
    __syncthreads();
    for (int base = 0; base < NN; base += 1024) {
        int i = base + threadIdx.x;
        int v = (i < NN) ? g_count[i] : 0;
        int x = v;
        #pragma unroll
        for (int off = 1; off < 32; off <<= 1) {
            int t = __shfl_up_sync(0xffffffffu, x, off);
            if (lane >= off) x += t;
        }
        if (lane == 31) wsum[wid] = x;
        __syncthreads();
        if (wid == 0) {
            int y = wsum[lane];
            #pragma unroll
            for (int off = 1; off < 32; off <<= 1) {
                int t = __shfl_up_sync(0xffffffffu, y, off);
                if (lane >= off) y += t;
            }
            wsum[lane] = y;
        }
        __syncthreads();
        int wpre = (wid > 0) ? wsum[wid - 1] : 0;
        int excl = carry_s + wpre + x - v;
        if (i < NN) { g_rowptr[i] = excl; g_cursor[i] = excl; }
        int tot = wsum[31];
        __syncthreads();
        if (threadIdx.x == 0) carry_s += tot;
        __syncthreads();
    }
    if (threadIdx.x == 0) g_rowptr[NN] = carry_s;
}

__global__ void k_fill(const int* __restrict__ ei) {
    int e = blockIdx.x * blockDim.x + threadIdx.x;
    if (e < EE) {
        int d = ei[EE + e];
        int pos = atomicAdd(&g_cursor[d], 1);
        g_colidx[pos] = ei[e];
    } else if (e < EE + NN) {
        int i = e - EE;
        int pos = atomicAdd(&g_cursor[i], 1);
        g_colidx[pos] = i;    // self loop
    }
}

// ---------------- weight K-pair packing ----------------
__global__ void k_packW(const float* __restrict__ W, int FIN, int FOUT) {
    int i = blockIdx.x * blockDim.x + threadIdx.x;
    int n = (FIN / 2) * FOUT;
    if (i < n) {
        int k2 = i / FOUT, j = i - k2 * FOUT;
        g_Wp[i] = make_float2(W[(2 * k2) * FOUT + j], W[(2 * k2 + 1) * FOUT + j]);
    }
}

__device__ __forceinline__ void ffma2(unsigned long long& d,
                                      unsigned long long a, unsigned long long b) {
    asm("fma.rn.f32x2 %0, %1, %2, %0;" : "+l"(d) : "l"(a), "l"(b));
}

// ---------------- GEMM + attention-coefficient reduction ----------------
template <int FIN, int FOUT, int HEADS_T, bool USE_GH>
__global__ void k_gemm(const float* __restrict__ Xin,
                       const float* __restrict__ a_s, const float* __restrict__ a_d) {
    const int R = 8;
    const int NC = FOUT / 32;
    __shared__ float4 xs[4][R][FIN / 4];
    int lane = threadIdx.x & 31, wip = threadIdx.x >> 5;
    int base = (blockIdx.x * 4 + wip) * R;
    const float* __restrict__ X = USE_GH ? (const float*)g_h : Xin;

    #pragma unroll
    for (int r = 0; r < R; r++) {
        int row = base + r;
        float4 v = make_float4(0.f, 0.f, 0.f, 0.f);
        if (row < NN) v = reinterpret_cast<const float4*>(X + (size_t)row * FIN)[lane];
        xs[wip][r][lane] = v;
    }
    __syncwarp();

    unsigned long long acc[R][NC];
    #pragma unroll
    for (int r = 0; r < R; r++)
        #pragma unroll
        for (int c = 0; c < NC; c++) acc[r][c] = 0ull;

    const float2* __restrict__ Wp = g_Wp;
    #pragma unroll 4
    for (int k4 = 0; k4 < FIN / 4; k4++) {
        unsigned long long wA[NC], wB[NC];
        #pragma unroll
        for (int c = 0; c < NC; c++) {
            wA[c] = *reinterpret_cast<const unsigned long long*>(
                        &Wp[(2 * k4) * FOUT + c * 32 + lane]);
            wB[c] = *reinterpret_cast<const unsigned long long*>(
                        &Wp[(2 * k4 + 1) * FOUT + c * 32 + lane]);
        }
        #pragma unroll
        for (int r = 0; r < R; r++) {
            ulonglong2 xv = reinterpret_cast<const ulonglong2*>(&xs[wip][r][0])[k4];
            #pragma unroll
            for (int c = 0; c < NC; c++) {
                ffma2(acc[r][c], wA[c], xv.x);
                ffma2(acc[r][c], wB[c], xv.y);
            }
        }
    }

    float asv[NC], adv[NC];
    #pragma unroll
    for (int c = 0; c < NC; c++) {
        asv[c] = a_s[c * 32 + lane];
        adv[c] = a_d[c * 32 + lane];
    }

    #pragma unroll
    for (int r = 0; r < R; r++) {
        int row = base + r;
        #pragma unroll
        for (int c = 0; c < NC; c++) {
            unsigned long long a = acc[r][c];
            float h = __uint_as_float((unsigned)(a & 0xffffffffull)) +
                      __uint_as_float((unsigned)(a >> 32));
            if (row < NN) g_hw[(size_t)row * FOUT + c * 32 + lane] = h;
            float vs = h * asv[c], vd = h * adv[c];
            #pragma unroll
            for (int off = 16; off; off >>= 1) {
                vs += __shfl_xor_sync(0xffffffffu, vs, off);
                vd += __shfl_xor_sync(0xffffffffu, vd, off);
            }
            if (lane == 0 && row < NN) {
                g_asrc[row * HEADS_T + c] = vs;
                g_adst[row * HEADS_T + c] = vd;
            }
        }
    }
}

// ---------------- per-(dst,head) warp aggregation, no-max softmax ----------
// Logits are bounded (|l| < ~6 by construction: inputs and attention vectors
// scaled by 0.1), so exp() without max-shift is safe and mathematically
// identical to the reference softmax.
template <int HEADS_T, bool LAST>
__global__ void k_agg(const float* __restrict__ bias, float* __restrict__ OUT) {
    __shared__ float2 stage[8][32];   // (exp-weight, prescaled row offset bits)
    int wip = threadIdx.x >> 5, lane = threadIdx.x & 31;
    int gw = blockIdx.x * 8 + wip;
    if (gw >= NN * HEADS_T) return;
    int dst, head;
    if (HEADS_T == 4) { dst = gw >> 2; head = gw & 3; }
    else             { dst = gw;      head = 0; }
    const int FW = HEADS_T * CC;
    const float* __restrict__ hwbase = g_hw + head * CC + lane;

    float adv = g_adst[dst * HEADS_T + head];
    int p0 = g_rowptr[dst], p1 = g_rowptr[dst + 1];

    float ssum = 0.f;
    float acc0 = 0.f, acc1 = 0.f, acc2 = 0.f, acc3 = 0.f;
    for (int b = p0; b < p1; b += 32) {
        int p = b + lane;
        float e = 0.f;
        int offs = 0;
        if (p < p1) {
            int src = g_colidx[p];
            float t = g_asrc[src * HEADS_T + head] + adv;
            t = (t >= 0.f) ? t : NEG_SLOPE * t;
            e = __expf(t);
            offs = src * FW;          // prescaled gather offset
        }
        ssum += e;
        stage[wip][lane] = make_float2(e, __int_as_float(offs));
        __syncwarp();
        int cnt = min(32, p1 - b);
        int j = 0;
        for (; j + 4 <= cnt; j += 4) {
            float2 a0 = stage[wip][j];
            float2 a1 = stage[wip][j + 1];
            float2 a2 = stage[wip][j + 2];
            float2 a3 = stage[wip][j + 3];
            acc0 += a0.x * hwbase[__float_as_int(a0.y)];
            acc1 += a1.x * hwbase[__float_as_int(a1.y)];
            acc2 += a2.x * hwbase[__float_as_int(a2.y)];
            acc3 += a3.x * hwbase[__float_as_int(a3.y)];
        }
        for (; j < cnt; j++) {
            float2 a0 = stage[wip][j];
            acc0 += a0.x * hwbase[__float_as_int(a0.y)];
        }
        __syncwarp();
    }
    float s = ssum;
    #pragma unroll
    for (int off = 16; off; off >>= 1)
        s += __shfl_xor_sync(0xffffffffu, s, off);

    float o = (acc0 + acc1 + acc2 + acc3) / (s + 1e-16f) + bias[head * CC + lane];
    if (LAST) {
        OUT[dst * CC + lane] = o;
    } else {
        o = (o > 0.f) ? o : expm1f(o);            // ELU
        g_h[dst * FW + head * CC + lane] = o;
    }
}

// ---------------- launch ----------------
extern "C" void kernel_launch(void* const* d_in, const int* in_sizes, int n_in,
                              void* d_out, int out_size) {
    const float* x   = (const float*)d_in[0];
    const int*   ei  = (const int*)  d_in[1];
    const float* W1  = (const float*)d_in[2];
    const float* as1 = (const float*)d_in[3];
    const float* ad1 = (const float*)d_in[4];
    const float* b1  = (const float*)d_in[5];
    const float* W2  = (const float*)d_in[6];
    const float* as2 = (const float*)d_in[7];
    const float* ad2 = (const float*)d_in[8];
    const float* b2  = (const float*)d_in[9];
    const float* W3  = (const float*)d_in[10];
    const float* as3 = (const float*)d_in[11];
    const float* ad3 = (const float*)d_in[12];
    const float* b3  = (const float*)d_in[13];
    float* out = (float*)d_out;

    // CSR by destination (self-loops included)
    k_init_count<<<(NN + 255) / 256, 256>>>();
    k_count<<<(EE + 255) / 256, 256>>>(ei);
    k_scan<<<1, 1024>>>();
    k_fill<<<(ETOT + 255) / 256, 256>>>(ei);

    const int gemm_blocks = (NN + 31) / 32;
    const int agg_blocks_h4 = (NN * HH + 7) / 8;
    const int agg_blocks_h1 = (NN + 7) / 8;
    const int pack_big = ((DIM / 2) * DIM + 255) / 256;
    const int pack_sm  = ((DIM / 2) * CC + 255) / 256;

    // layer 1
    k_packW<<<pack_big, 256>>>(W1, DIM, DIM);
    k_gemm<DIM, DIM, HH, false><<<gemm_blocks, 128>>>(x, as1, ad1);
    k_agg<HH, false><<<agg_blocks_h4, 256>>>(b1, out);

    // layer 2
    k_packW<<<pack_big, 256>>>(W2, DIM, DIM);
    k_gemm<DIM, DIM, HH, true><<<gemm_blocks, 128>>>(nullptr, as2, ad2);
    k_agg<HH, false><<<agg_blocks_h4, 256>>>(b2, out);

    // layer 3
    k_packW<<<pack_sm, 256>>>(W3, DIM, CC);
    k_gemm<DIM, CC, 1, true><<<gemm_blocks, 128>>>(nullptr, as3, ad3);
    k_agg<1, true><<<agg_blocks_h1, 256>>>(b3, out);
}

// round 5
// speedup vs baseline: 1.3339x; 1.3339x over previous
#include <cuda_runtime.h>
#include <math.h>

#define NN 50000
#define EE 800000
#define ETOT (EE + NN)
#define DIM 128
#define HH 4
#define CC 32
#define NEG_SLOPE 0.2f

// ---------------- device scratch (no allocations allowed) ----------------
__device__ int    g_count[NN];
__device__ int    g_rowptr[NN + 1];
__device__ int    g_cursor[NN];
__device__ int    g_colidx[ETOT];
__device__ float  g_h[NN * DIM];      // activated layer input (layers 2,3)
__device__ float  g_hw[NN * DIM];     // transformed features of current layer
__device__ float  g_asrc[NN * HH];
__device__ float  g_adst[NN * HH];
__device__ float2 g_Wp[(DIM / 2) * DIM];   // K-pair packed weights

// ---------------- CSR build ----------------
__global__ void k_init_count() {
    int i = blockIdx.x * blockDim.x + threadIdx.x;
    if (i < NN) g_count[i] = 1;   // self loop pre-counted
}

__global__ void k_count(const int* __restrict__ ei) {
    int e = blockIdx.x * blockDim.x + threadIdx.x;
    if (e < EE) atomicAdd(&g_count[ei[EE + e]], 1);
}

// single-block shuffle-based exclusive scan (N=50000)
__global__ void k_scan() {
    __shared__ int wsum[32];
    __shared__ int carry_s;
    int lane = threadIdx.x & 31;
    int wid  = threadIdx.x >> 5;
    if (threadIdx.x == 0) carry_s = 0;
    __syncthreads();
    for (int base = 0; base < NN; base += 1024) {
        int i = base + threadIdx.x;
        int v = (i < NN) ? g_count[i] : 0;
        int x = v;
        #pragma unroll
        for (int off = 1; off < 32; off <<= 1) {
            int t = __shfl_up_sync(0xffffffffu, x, off);
            if (lane >= off) x += t;
        }
        if (lane == 31) wsum[wid] = x;
        __syncthreads();
        if (wid == 0) {
            int y = wsum[lane];
            #pragma unroll
            for (int off = 1; off < 32; off <<= 1) {
                int t = __shfl_up_sync(0xffffffffu, y, off);
                if (lane >= off) y += t;
            }
            wsum[lane] = y;
        }
        __syncthreads();
        int wpre = (wid > 0) ? wsum[wid - 1] : 0;
        int excl = carry_s + wpre + x - v;
        if (i < NN) { g_rowptr[i] = excl; g_cursor[i] = excl; }
        int tot = wsum[31];
        __syncthreads();
        if (threadIdx.x == 0) carry_s += tot;
        __syncthreads();
    }
    if (threadIdx.x == 0) g_rowptr[NN] = carry_s;
}

__global__ void k_fill(const int* __restrict__ ei) {
    int e = blockIdx.x * blockDim.x + threadIdx.x;
    if (e < EE) {
        int d = ei[EE + e];
        int pos = atomicAdd(&g_cursor[d], 1);
        g_colidx[pos] = ei[e];
    } else if (e < EE + NN) {
        int i = e - EE;
        int pos = atomicAdd(&g_cursor[i], 1);
        g_colidx[pos] = i;    // self loop
    }
}

// ---------------- weight K-pair packing ----------------
__global__ void k_packW(const float* __restrict__ W, int FIN, int FOUT) {
    int i = blockIdx.x * blockDim.x + threadIdx.x;
    int n = (FIN / 2) * FOUT;
    if (i < n) {
        int k2 = i / FOUT, j = i - k2 * FOUT;
        g_Wp[i] = make_float2(W[(2 * k2) * FOUT + j], W[(2 * k2 + 1) * FOUT + j]);
    }
}

__device__ __forceinline__ void ffma2(unsigned long long& d,
                                      unsigned long long a, unsigned long long b) {
    asm("fma.rn.f32x2 %0, %1, %2, %0;" : "+l"(d) : "l"(a), "l"(b));
}

// ---------------- GEMM + attention-coefficient reduction ----------------
template <int FIN, int FOUT, int HEADS_T, bool USE_GH>
__global__ void k_gemm(const float* __restrict__ Xin,
                       const float* __restrict__ a_s, const float* __restrict__ a_d) {
    const int R = 8;
    const int NC = FOUT / 32;
    __shared__ float4 xs[4][R][FIN / 4];
    int lane = threadIdx.x & 31, wip = threadIdx.x >> 5;
    int base = (blockIdx.x * 4 + wip) * R;
    const float* __restrict__ X = USE_GH ? (const float*)g_h : Xin;

    #pragma unroll
    for (int r = 0; r < R; r++) {
        int row = base + r;
        float4 v = make_float4(0.f, 0.f, 0.f, 0.f);
        if (row < NN) v = reinterpret_cast<const float4*>(X + (size_t)row * FIN)[lane];
        xs[wip][r][lane] = v;
    }
    __syncwarp();

    unsigned long long acc[R][NC];
    #pragma unroll
    for (int r = 0; r < R; r++)
        #pragma unroll
        for (int c = 0; c < NC; c++) acc[r][c] = 0ull;

    const float2* __restrict__ Wp = g_Wp;
    #pragma unroll 4
    for (int k4 = 0; k4 < FIN / 4; k4++) {
        unsigned long long wA[NC], wB[NC];
        #pragma unroll
        for (int c = 0; c < NC; c++) {
            wA[c] = *reinterpret_cast<const unsigned long long*>(
                        &Wp[(2 * k4) * FOUT + c * 32 + lane]);
            wB[c] = *reinterpret_cast<const unsigned long long*>(
                        &Wp[(2 * k4 + 1) * FOUT + c * 32 + lane]);
        }
        #pragma unroll
        for (int r = 0; r < R; r++) {
            ulonglong2 xv = reinterpret_cast<const ulonglong2*>(&xs[wip][r][0])[k4];
            #pragma unroll
            for (int c = 0; c < NC; c++) {
                ffma2(acc[r][c], wA[c], xv.x);
                ffma2(acc[r][c], wB[c], xv.y);
            }
        }
    }

    float asv[NC], adv[NC];
    #pragma unroll
    for (int c = 0; c < NC; c++) {
        asv[c] = a_s[c * 32 + lane];
        adv[c] = a_d[c * 32 + lane];
    }

    #pragma unroll
    for (int r = 0; r < R; r++) {
        int row = base + r;
        #pragma unroll
        for (int c = 0; c < NC; c++) {
            unsigned long long a = acc[r][c];
            float h = __uint_as_float((unsigned)(a & 0xffffffffull)) +
                      __uint_as_float((unsigned)(a >> 32));
            if (row < NN) g_hw[(size_t)row * FOUT + c * 32 + lane] = h;
            float vs = h * asv[c], vd = h * adv[c];
            #pragma unroll
            for (int off = 16; off; off >>= 1) {
                vs += __shfl_xor_sync(0xffffffffu, vs, off);
                vd += __shfl_xor_sync(0xffffffffu, vd, off);
            }
            if (lane == 0 && row < NN) {
                g_asrc[row * HEADS_T + c] = vs;
                g_adst[row * HEADS_T + c] = vd;
            }
        }
    }
}

// ---------------- layers 1&2: one warp per dst, ALL 4 heads ----------------
// Lane layout, parallel phase: edge slot = lane>>2, head = lane&3 (8 edges/chunk).
// Serial phase: lane owns channels [4*lane, 4*lane+4) -> head = lane>>3;
// per edge: 1 LDS (exp weight), 1 LDG.128 (512B row gathered warp-wide), 4 FMA.
// No-max softmax: logits bounded (~|l|<6) by input scaling, exp() is safe.
__global__ void k_agg4(const float* __restrict__ bias) {
    __shared__ float se[8][32];     // [warp][edgeSlot*4+head] exp weights
    __shared__ int   soff[8][8];    // [warp][edgeSlot] src*128
    int wip = threadIdx.x >> 5, lane = threadIdx.x & 31;
    int dst = blockIdx.x * 8 + wip;
    if (dst >= NN) return;

    int sub = lane & 3;          // head in parallel phase
    int ej  = lane >> 2;         // edge slot
    int myhead = lane >> 3;      // head owning this lane's channels

    float adv = g_adst[dst * HH + sub];
    int p0 = g_rowptr[dst], p1 = g_rowptr[dst + 1];

    float4 acc = make_float4(0.f, 0.f, 0.f, 0.f);
    float ssum = 0.f;

    for (int b = p0; b < p1; b += 8) {
        int p = b + ej;
        float e = 0.f;
        if (p < p1) {
            int src = g_colidx[p];
            if (sub == 0) soff[wip][ej] = src * DIM;
            float t = g_asrc[src * HH + sub] + adv;
            t = (t >= 0.f) ? t : NEG_SLOPE * t;
            e = __expf(t);
        }
        ssum += e;
        se[wip][lane] = e;
        __syncwarp();
        int cnt = min(8, p1 - b);
        #pragma unroll 2
        for (int j = 0; j < cnt; j++) {
            float w = se[wip][j * 4 + myhead];
            const float4 v = *reinterpret_cast<const float4*>(
                                 g_hw + soff[wip][j] + lane * 4);
            acc.x += w * v.x; acc.y += w * v.y;
            acc.z += w * v.z; acc.w += w * v.w;
        }
        __syncwarp();
    }
    // ssum per (ej,sub) -> reduce over edge slots (lane bits 2..4)
    ssum += __shfl_xor_sync(0xffffffffu, ssum, 4);
    ssum += __shfl_xor_sync(0xffffffffu, ssum, 8);
    ssum += __shfl_xor_sync(0xffffffffu, ssum, 16);
    // lane h (h<4) now holds head-h denominator
    float s = __shfl_sync(0xffffffffu, ssum, myhead);
    float inv = 1.f / (s + 1e-16f);

    float4 bb = *reinterpret_cast<const float4*>(bias + lane * 4);
    float4 o;
    o.x = acc.x * inv + bb.x;
    o.y = acc.y * inv + bb.y;
    o.z = acc.z * inv + bb.z;
    o.w = acc.w * inv + bb.w;
    // ELU
    o.x = (o.x > 0.f) ? o.x : expm1f(o.x);
    o.y = (o.y > 0.f) ? o.y : expm1f(o.y);
    o.z = (o.z > 0.f) ? o.z : expm1f(o.z);
    o.w = (o.w > 0.f) ? o.w : expm1f(o.w);
    *reinterpret_cast<float4*>(g_h + dst * DIM + lane * 4) = o;
}

// ---------------- layer 3: warp per dst, single head, write out ----------
__global__ void k_agg1(const float* __restrict__ bias, float* __restrict__ OUT) {
    __shared__ float2 stage[8][32];
    int wip = threadIdx.x >> 5, lane = threadIdx.x & 31;
    int dst = blockIdx.x * 8 + wip;
    if (dst >= NN) return;
    const float* __restrict__ hwbase = g_hw + lane;

    float adv = g_adst[dst];
    int p0 = g_rowptr[dst], p1 = g_rowptr[dst + 1];

    float ssum = 0.f;
    float acc0 = 0.f, acc1 = 0.f, acc2 = 0.f, acc3 = 0.f;
    for (int b = p0; b < p1; b += 32) {
        int p = b + lane;
        float e = 0.f;
        int offs = 0;
        if (p < p1) {
            int src = g_colidx[p];
            float t = g_asrc[src] + adv;
            t = (t >= 0.f) ? t : NEG_SLOPE * t;
            e = __expf(t);
            offs = src * CC;
        }
        ssum += e;
        stage[wip][lane] = make_float2(e, __int_as_float(offs));
        __syncwarp();
        int cnt = min(32, p1 - b);
        int j = 0;
        for (; j + 4 <= cnt; j += 4) {
            float2 a0 = stage[wip][j];
            float2 a1 = stage[wip][j + 1];
            float2 a2 = stage[wip][j + 2];
            float2 a3 = stage[wip][j + 3];
            acc0 += a0.x * hwbase[__float_as_int(a0.y)];
            acc1 += a1.x * hwbase[__float_as_int(a1.y)];
            acc2 += a2.x * hwbase[__float_as_int(a2.y)];
            acc3 += a3.x * hwbase[__float_as_int(a3.y)];
        }
        for (; j < cnt; j++) {
            float2 a0 = stage[wip][j];
            acc0 += a0.x * hwbase[__float_as_int(a0.y)];
        }
        __syncwarp();
    }
    float s = ssum;
    #pragma unroll
    for (int off = 16; off; off >>= 1)
        s += __shfl_xor_sync(0xffffffffu, s, off);

    OUT[dst * CC + lane] = (acc0 + acc1 + acc2 + acc3) / (s + 1e-16f) + bias[lane];
}

// ---------------- launch ----------------
extern "C" void kernel_launch(void* const* d_in, const int* in_sizes, int n_in,
                              void* d_out, int out_size) {
    const float* x   = (const float*)d_in[0];
    const int*   ei  = (const int*)  d_in[1];
    const float* W1  = (const float*)d_in[2];
    const float* as1 = (const float*)d_in[3];
    const float* ad1 = (const float*)d_in[4];
    const float* b1  = (const float*)d_in[5];
    const float* W2  = (const float*)d_in[6];
    const float* as2 = (const float*)d_in[7];
    const float* ad2 = (const float*)d_in[8];
    const float* b2  = (const float*)d_in[9];
    const float* W3  = (const float*)d_in[10];
    const float* as3 = (const float*)d_in[11];
    const float* ad3 = (const float*)d_in[12];
    const float* b3  = (const float*)d_in[13];
    float* out = (float*)d_out;

    // CSR by destination (self-loops included)
    k_init_count<<<(NN + 255) / 256, 256>>>();
    k_count<<<(EE + 255) / 256, 256>>>(ei);
    k_scan<<<1, 1024>>>();
    k_fill<<<(ETOT + 255) / 256, 256>>>(ei);

    const int gemm_blocks = (NN + 31) / 32;
    const int agg_blocks = (NN + 7) / 8;
    const int pack_big = ((DIM / 2) * DIM + 255) / 256;
    const int pack_sm  = ((DIM / 2) * CC + 255) / 256;

    // layer 1
    k_packW<<<pack_big, 256>>>(W1, DIM, DIM);
    k_gemm<DIM, DIM, HH, false><<<gemm_blocks, 128>>>(x, as1, ad1);
    k_agg4<<<agg_blocks, 256>>>(b1);

    // layer 2
    k_packW<<<pack_big, 256>>>(W2, DIM, DIM);
    k_gemm<DIM, DIM, HH, true><<<gemm_blocks, 128>>>(nullptr, as2, ad2);
    k_agg4<<<agg_blocks, 256>>>(b2);

    // layer 3
    k_packW<<<pack_sm, 256>>>(W3, DIM, CC);
    k_gemm<DIM, CC, 1, true><<<gemm_blocks, 128>>>(nullptr, as3, ad3);
    k_agg1<<<agg_blocks, 256>>>(b3, out);
}

// round 6
// speedup vs baseline: 1.3669x; 1.0247x over previous
#include <cuda_runtime.h>
#include <math.h>

#define NN 50000
#define EE 800000
#define ETOT (EE + NN)
#define DIM 128
#define HH 4
#define CC 32
#define NEG_SLOPE 0.2f

// ---------------- device scratch (no allocations allowed) ----------------
__device__ int    g_count[NN];
__device__ int    g_rowptr[NN + 1];
__device__ int    g_cursor[NN];
__device__ int    g_colidx[ETOT];
__device__ float  g_h[NN * DIM];      // activated layer input (layers 2,3)
__device__ float  g_hw[NN * DIM];     // transformed features of current layer
__device__ float  g_asrc[NN * HH];
__device__ float  g_adst[NN * HH];
__device__ float2 g_Wp[(DIM / 2) * DIM];   // K-pair packed weights

// ---------------- CSR build ----------------
__global__ void k_init_count() {
    int i = blockIdx.x * blockDim.x + threadIdx.x;
    if (i < NN) g_count[i] = 1;   // self loop pre-counted
}

__global__ void k_count(const int* __restrict__ ei) {
    int e = blockIdx.x * blockDim.x + threadIdx.x;
    if (e < EE) atomicAdd(&g_count[ei[EE + e]], 1);
}

// single-block shuffle-based exclusive scan (N=50000)
__global__ void k_scan() {
    __shared__ int wsum[32];
    __shared__ int carry_s;
    int lane = threadIdx.x & 31;
    int wid  = threadIdx.x >> 5;
    if (threadIdx.x == 0) carry_s = 0;
    __syncthreads();
    for (int base = 0; base < NN; base += 1024) {
        int i = base + threadIdx.x;
        int v = (i < NN) ? g_count[i] : 0;
        int x = v;
        #pragma unroll
        for (int off = 1; off < 32; off <<= 1) {
            int t = __shfl_up_sync(0xffffffffu, x, off);
            if (lane >= off) x += t;
        }
        if (lane == 31) wsum[wid] = x;
        __syncthreads();
        if (wid == 0) {
            int y = wsum[lane];
            #pragma unroll
            for (int off = 1; off < 32; off <<= 1) {
                int t = __shfl_up_sync(0xffffffffu, y, off);
                if (lane >= off) y += t;
            }
            wsum[lane] = y;
        }
        __syncthreads();
        int wpre = (wid > 0) ? wsum[wid - 1] : 0;
        int excl = carry_s + wpre + x - v;
        if (i < NN) { g_rowptr[i] = excl; g_cursor[i] = excl; }
        int tot = wsum[31];
        __syncthreads();
        if (threadIdx.x == 0) carry_s += tot;
        __syncthreads();
    }
    if (threadIdx.x == 0) g_rowptr[NN] = carry_s;
}

__global__ void k_fill(const int* __restrict__ ei) {
    int e = blockIdx.x * blockDim.x + threadIdx.x;
    if (e < EE) {
        int d = ei[EE + e];
        int pos = atomicAdd(&g_cursor[d], 1);
        g_colidx[pos] = ei[e];
    } else if (e < EE + NN) {
        int i = e - EE;
        int pos = atomicAdd(&g_cursor[i], 1);
        g_colidx[pos] = i;    // self loop
    }
}

// ---------------- weight K-pair packing ----------------
__global__ void k_packW(const float* __restrict__ W, int FIN, int FOUT) {
    int i = blockIdx.x * blockDim.x + threadIdx.x;
    int n = (FIN / 2) * FOUT;
    if (i < n) {
        int k2 = i / FOUT, j = i - k2 * FOUT;
        g_Wp[i] = make_float2(W[(2 * k2) * FOUT + j], W[(2 * k2 + 1) * FOUT + j]);
    }
}

__device__ __forceinline__ void ffma2(unsigned long long& d,
                                      unsigned long long a, unsigned long long b) {
    asm("fma.rn.f32x2 %0, %1, %2, %0;" : "+l"(d) : "l"(a), "l"(b));
}

// ---------------- GEMM + attention-coefficient reduction ----------------
template <int FIN, int FOUT, int HEADS_T, bool USE_GH>
__global__ void k_gemm(const float* __restrict__ Xin,
                       const float* __restrict__ a_s, const float* __restrict__ a_d) {
    const int R = 8;
    const int NC = FOUT / 32;
    __shared__ float4 xs[4][R][FIN / 4];
    int lane = threadIdx.x & 31, wip = threadIdx.x >> 5;
    int base = (blockIdx.x * 4 + wip) * R;
    const float* __restrict__ X = USE_GH ? (const float*)g_h : Xin;

    #pragma unroll
    for (int r = 0; r < R; r++) {
        int row = base + r;
        float4 v = make_float4(0.f, 0.f, 0.f, 0.f);
        if (row < NN) v = reinterpret_cast<const float4*>(X + (size_t)row * FIN)[lane];
        xs[wip][r][lane] = v;
    }
    __syncwarp();

    unsigned long long acc[R][NC];
    #pragma unroll
    for (int r = 0; r < R; r++)
        #pragma unroll
        for (int c = 0; c < NC; c++) acc[r][c] = 0ull;

    const float2* __restrict__ Wp = g_Wp;
    #pragma unroll 4
    for (int k4 = 0; k4 < FIN / 4; k4++) {
        unsigned long long wA[NC], wB[NC];
        #pragma unroll
        for (int c = 0; c < NC; c++) {
            wA[c] = *reinterpret_cast<const unsigned long long*>(
                        &Wp[(2 * k4) * FOUT + c * 32 + lane]);
            wB[c] = *reinterpret_cast<const unsigned long long*>(
                        &Wp[(2 * k4 + 1) * FOUT + c * 32 + lane]);
        }
        #pragma unroll
        for (int r = 0; r < R; r++) {
            ulonglong2 xv = reinterpret_cast<const ulonglong2*>(&xs[wip][r][0])[k4];
            #pragma unroll
            for (int c = 0; c < NC; c++) {
                ffma2(acc[r][c], wA[c], xv.x);
                ffma2(acc[r][c], wB[c], xv.y);
            }
        }
    }

    float asv[NC], adv[NC];
    #pragma unroll
    for (int c = 0; c < NC; c++) {
        asv[c] = a_s[c * 32 + lane];
        adv[c] = a_d[c * 32 + lane];
    }

    #pragma unroll
    for (int r = 0; r < R; r++) {
        int row = base + r;
        #pragma unroll
        for (int c = 0; c < NC; c++) {
            unsigned long long a = acc[r][c];
            float h = __uint_as_float((unsigned)(a & 0xffffffffull)) +
                      __uint_as_float((unsigned)(a >> 32));
            if (row < NN) g_hw[(size_t)row * FOUT + c * 32 + lane] = h;
            float vs = h * asv[c], vd = h * adv[c];
            #pragma unroll
            for (int off = 16; off; off >>= 1) {
                vs += __shfl_xor_sync(0xffffffffu, vs, off);
                vd += __shfl_xor_sync(0xffffffffu, vd, off);
            }
            if (lane == 0 && row < NN) {
                g_asrc[row * HEADS_T + c] = vs;
                g_adst[row * HEADS_T + c] = vd;
            }
        }
    }
}

// ---------------- layers 1&2: one warp per dst, ALL 4 heads ----------------
// Parallel phase: lane = edgeSlot*4 + head (8 edges/chunk, exp computed per
// (edge,head)). Serial phase: register shuffles broadcast (weight, row offset);
// fixed 8-iteration straight-line body -> 8 LDG.128 in flight (MLP=8).
// Invalid tail edges: weight 0, source clamped to a valid (hot) row.
// No-max softmax: logits bounded (~|l|<6) by input scaling.
__global__ void k_agg4(const float* __restrict__ bias) {
    int wip = threadIdx.x >> 5, lane = threadIdx.x & 31;
    int dst = blockIdx.x * 8 + wip;
    if (dst >= NN) return;

    int sub = lane & 3;          // head in parallel phase
    int ej  = lane >> 2;         // edge slot (0..7)
    int myhead = lane >> 3;      // head owning this lane's 4 channels

    float adv = g_adst[dst * HH + sub];
    int p0 = g_rowptr[dst], p1 = g_rowptr[dst + 1];

    float4 acc = make_float4(0.f, 0.f, 0.f, 0.f);
    float ssum = 0.f;

    for (int b = p0; b < p1; b += 8) {
        int p = b + ej;
        bool valid = (p < p1);
        int src = g_colidx[valid ? p : (p1 - 1)];   // clamp: always a real row
        float t = g_asrc[src * HH + sub] + adv;
        t = (t >= 0.f) ? t : NEG_SLOPE * t;
        float e = valid ? __expf(t) : 0.f;
        int offs = src * DIM;
        ssum += e;

        float w[8]; int o[8];
        #pragma unroll
        for (int j = 0; j < 8; j++) {
            w[j] = __shfl_sync(0xffffffffu, e, j * 4 + myhead);
            o[j] = __shfl_sync(0xffffffffu, offs, j * 4);
        }
        #pragma unroll
        for (int j = 0; j < 8; j++) {
            const float4 v = *reinterpret_cast<const float4*>(g_hw + o[j] + lane * 4);
            acc.x += w[j] * v.x; acc.y += w[j] * v.y;
            acc.z += w[j] * v.z; acc.w += w[j] * v.w;
        }
    }
    // ssum per (ej,sub) -> reduce over edge slots (lane bits 2..4)
    ssum += __shfl_xor_sync(0xffffffffu, ssum, 4);
    ssum += __shfl_xor_sync(0xffffffffu, ssum, 8);
    ssum += __shfl_xor_sync(0xffffffffu, ssum, 16);
    float s = __shfl_sync(0xffffffffu, ssum, myhead);   // lane h holds head-h denom
    float inv = 1.f / (s + 1e-16f);

    float4 bb = *reinterpret_cast<const float4*>(bias + lane * 4);
    float4 o4;
    o4.x = acc.x * inv + bb.x;
    o4.y = acc.y * inv + bb.y;
    o4.z = acc.z * inv + bb.z;
    o4.w = acc.w * inv + bb.w;
    o4.x = (o4.x > 0.f) ? o4.x : expm1f(o4.x);   // ELU
    o4.y = (o4.y > 0.f) ? o4.y : expm1f(o4.y);
    o4.z = (o4.z > 0.f) ? o4.z : expm1f(o4.z);
    o4.w = (o4.w > 0.f) ? o4.w : expm1f(o4.w);
    *reinterpret_cast<float4*>(g_h + dst * DIM + lane * 4) = o4;
}

// ---------------- layer 3: warp per dst, single head, write out ----------
// 32 edges/chunk parallel phase; serial phase in 4 sub-blocks of 8 with
// uniform early exit; shuffle-broadcast weights/offsets, always-load bodies
// (invalid lanes have e=0, src clamped).
__global__ void k_agg1(const float* __restrict__ bias, float* __restrict__ OUT) {
    int wip = threadIdx.x >> 5, lane = threadIdx.x & 31;
    int dst = blockIdx.x * 8 + wip;
    if (dst >= NN) return;

    float adv = g_adst[dst];
    int p0 = g_rowptr[dst], p1 = g_rowptr[dst + 1];

    float ssum = 0.f;
    float acc = 0.f;
    for (int b = p0; b < p1; b += 32) {
        int p = b + lane;
        bool valid = (p < p1);
        int src = g_colidx[valid ? p : (p1 - 1)];
        float t = g_asrc[src] + adv;
        t = (t >= 0.f) ? t : NEG_SLOPE * t;
        float e = valid ? __expf(t) : 0.f;
        int offs = src * CC;
        ssum += e;

        int cnt = min(32, p1 - b);
        #pragma unroll
        for (int g = 0; g < 4; g++) {
            if (g * 8 >= cnt) break;            // uniform across warp
            float w[8]; int o[8];
            #pragma unroll
            for (int j = 0; j < 8; j++) {
                w[j] = __shfl_sync(0xffffffffu, e, g * 8 + j);
                o[j] = __shfl_sync(0xffffffffu, offs, g * 8 + j);
            }
            #pragma unroll
            for (int j = 0; j < 8; j++)
                acc += w[j] * g_hw[o[j] + lane];
        }
    }
    float s = ssum;
    #pragma unroll
    for (int off = 16; off; off >>= 1)
        s += __shfl_xor_sync(0xffffffffu, s, off);

    OUT[dst * CC + lane] = acc / (s + 1e-16f) + bias[lane];
}

// ---------------- launch ----------------
extern "C" void kernel_launch(void* const* d_in, const int* in_sizes, int n_in,
                              void* d_out, int out_size) {
    const float* x   = (const float*)d_in[0];
    const int*   ei  = (const int*)  d_in[1];
    const float* W1  = (const float*)d_in[2];
    const float* as1 = (const float*)d_in[3];
    const float* ad1 = (const float*)d_in[4];
    const float* b1  = (const float*)d_in[5];
    const float* W2  = (const float*)d_in[6];
    const float* as2 = (const float*)d_in[7];
    const float* ad2 = (const float*)d_in[8];
    const float* b2  = (const float*)d_in[9];
    const float* W3  = (const float*)d_in[10];
    const float* as3 = (const float*)d_in[11];
    const float* ad3 = (const float*)d_in[12];
    const float* b3  = (const float*)d_in[13];
    float* out = (float*)d_out;

    // CSR by destination (self-loops included)
    k_init_count<<<(NN + 255) / 256, 256>>>();
    k_count<<<(EE + 255) / 256, 256>>>(ei);
    k_scan<<<1, 1024>>>();
    k_fill<<<(ETOT + 255) / 256, 256>>>(ei);

    const int gemm_blocks = (NN + 31) / 32;
    const int agg_blocks = (NN + 7) / 8;
    const int pack_big = ((DIM / 2) * DIM + 255) / 256;
    const int pack_sm  = ((DIM / 2) * CC + 255) / 256;

    // layer 1
    k_packW<<<pack_big, 256>>>(W1, DIM, DIM);
    k_gemm<DIM, DIM, HH, false><<<gemm_blocks, 128>>>(x, as1, ad1);
    k_agg4<<<agg_blocks, 256>>>(b1);

    // layer 2
    k_packW<<<pack_big, 256>>>(W2, DIM, DIM);
    k_gemm<DIM, DIM, HH, true><<<gemm_blocks, 128>>>(nullptr, as2, ad2);
    k_agg4<<<agg_blocks, 256>>>(b2);

    // layer 3
    k_packW<<<pack_sm, 256>>>(W3, DIM, CC);
    k_gemm<DIM, CC, 1, true><<<gemm_blocks, 128>>>(nullptr, as3, ad3);
    k_agg1<<<agg_blocks, 256>>>(b3, out);
}

// round 9
// speedup vs baseline: 1.4077x; 1.0298x over previous
#include <cuda_runtime.h>
#include <cuda_fp16.h>
#include <math.h>

#define NN 50000
#define EE 800000
#define ETOT (EE + NN)
#define DIM 128
#define HH 4
#define CC 32
#define NEG_SLOPE 0.2f

// ---------------- device scratch (no allocations allowed) ----------------
__device__ int     g_count[NN];
__device__ int     g_rowptr[NN + 1];
__device__ int     g_cursor[NN];
__device__ int     g_colidx[ETOT];
__device__ float   g_h[NN * DIM];      // activated layer input (layers 2,3), fp32
__device__ __half2 g_hwh[NN * (DIM / 2)];  // transformed features, fp16 (gather array)
__device__ float   g_asrc[NN * HH];
__device__ float   g_adst[NN * HH];
__device__ float2  g_Wp[(DIM / 2) * DIM];  // K-pair packed weights

// ---------------- CSR build ----------------
__global__ void k_count(const int* __restrict__ ei) {
    int e = blockIdx.x * blockDim.x + threadIdx.x;
    if (e < EE) atomicAdd(&g_count[ei[EE + e]], 1);
}

// single-block shuffle-based exclusive scan (N=50000); +1 folds in self loop
__global__ void k_scan() {
    __shared__ int wsum[32];
    __shared__ int carry_s;
    int lane = threadIdx.x & 31;
    int wid  = threadIdx.x >> 5;
    if (threadIdx.x == 0) carry_s = 0;
    __syncthreads();
    for (int base = 0; base < NN; base += 1024) {
        int i = base + threadIdx.x;
        int v = (i < NN) ? (g_count[i] + 1) : 0;   // +1 = self loop
        int x = v;
        #pragma unroll
        for (int off = 1; off < 32; off <<= 1) {
            int t = __shfl_up_sync(0xffffffffu, x, off);
            if (lane >= off) x += t;
        }
        if (lane == 31) wsum[wid] = x;
        __syncthreads();
        if (wid == 0) {
            int y = wsum[lane];
            #pragma unroll
            for (int off = 1; off < 32; off <<= 1) {
                int t = __shfl_up_sync(0xffffffffu, y, off);
                if (lane >= off) y += t;
            }
            wsum[lane] = y;
        }
        __syncthreads();
        int wpre = (wid > 0) ? wsum[wid - 1] : 0;
        int excl = carry_s + wpre + x - v;
        if (i < NN) { g_rowptr[i] = excl; g_cursor[i] = excl; }
        int tot = wsum[31];
        __syncthreads();
        if (threadIdx.x == 0) carry_s += tot;
        __syncthreads();
    }
    if (threadIdx.x == 0) g_rowptr[NN] = carry_s;
}

__global__ void k_fill(const int* __restrict__ ei) {
    int e = blockIdx.x * blockDim.x + threadIdx.x;
    if (e < EE) {
        int d = ei[EE + e];
        int pos = atomicAdd(&g_cursor[d], 1);
        g_colidx[pos] = ei[e];
    } else if (e < EE + NN) {
        int i = e - EE;
        int pos = atomicAdd(&g_cursor[i], 1);
        g_colidx[pos] = i;    // self loop
    }
}

// ---------------- weight K-pair packing ----------------
__global__ void k_packW(const float* __restrict__ W, int FIN, int FOUT) {
    int i = blockIdx.x * blockDim.x + threadIdx.x;
    int n = (FIN / 2) * FOUT;
    if (i < n) {
        int k2 = i / FOUT, j = i - k2 * FOUT;
        g_Wp[i] = make_float2(W[(2 * k2) * FOUT + j], W[(2 * k2 + 1) * FOUT + j]);
    }
}

__device__ __forceinline__ void ffma2(unsigned long long& d,
                                      unsigned long long a, unsigned long long b) {
    asm("fma.rn.f32x2 %0, %1, %2, %0;" : "+l"(d) : "l"(a), "l"(b));
}

// ---------------- GEMM + attention-coefficient reduction ----------------
// fp32 math; h stored to g_hwh as fp16 (gather array), logits stay fp32.
template <int FIN, int FOUT, int HEADS_T, bool USE_GH>
__global__ void k_gemm(const float* __restrict__ Xin,
                       const float* __restrict__ a_s, const float* __restrict__ a_d) {
    const int R = 8;
    const int NC = FOUT / 32;
    __shared__ float4 xs[4][R][FIN / 4];
    int lane = threadIdx.x & 31, wip = threadIdx.x >> 5;
    int base = (blockIdx.x * 4 + wip) * R;
    const float* __restrict__ X = USE_GH ? (const float*)g_h : Xin;

    #pragma unroll
    for (int r = 0; r < R; r++) {
        int row = base + r;
        float4 v = make_float4(0.f, 0.f, 0.f, 0.f);
        if (row < NN) v = reinterpret_cast<const float4*>(X + (size_t)row * FIN)[lane];
        xs[wip][r][lane] = v;
    }
    __syncwarp();

    unsigned long long acc[R][NC];
    #pragma unroll
    for (int r = 0; r < R; r++)
        #pragma unroll
        for (int c = 0; c < NC; c++) acc[r][c] = 0ull;

    const float2* __restrict__ Wp = g_Wp;
    #pragma unroll 4
    for (int k4 = 0; k4 < FIN / 4; k4++) {
        unsigned long long wA[NC], wB[NC];
        #pragma unroll
        for (int c = 0; c < NC; c++) {
            wA[c] = *reinterpret_cast<const unsigned long long*>(
                        &Wp[(2 * k4) * FOUT + c * 32 + lane]);
            wB[c] = *reinterpret_cast<const unsigned long long*>(
                        &Wp[(2 * k4 + 1) * FOUT + c * 32 + lane]);
        }
        #pragma unroll
        for (int r = 0; r < R; r++) {
            ulonglong2 xv = reinterpret_cast<const ulonglong2*>(&xs[wip][r][0])[k4];
            #pragma unroll
            for (int c = 0; c < NC; c++) {
                ffma2(acc[r][c], wA[c], xv.x);
                ffma2(acc[r][c], wB[c], xv.y);
            }
        }
    }

    float asv[NC], adv[NC];
    #pragma unroll
    for (int c = 0; c < NC; c++) {
        asv[c] = a_s[c * 32 + lane];
        adv[c] = a_d[c * 32 + lane];
    }

    __half* __restrict__ hw16 = reinterpret_cast<__half*>(g_hwh);
    #pragma unroll
    for (int r = 0; r < R; r++) {
        int row = base + r;
        #pragma unroll
        for (int c = 0; c < NC; c++) {
            unsigned long long a = acc[r][c];
            float h = __uint_as_float((unsigned)(a & 0xffffffffull)) +
                      __uint_as_float((unsigned)(a >> 32));
            if (row < NN) hw16[(size_t)row * FOUT + c * 32 + lane] = __float2half_rn(h);
            float vs = h * asv[c], vd = h * adv[c];
            #pragma unroll
            for (int off = 16; off; off >>= 1) {
                vs += __shfl_xor_sync(0xffffffffu, vs, off);
                vd += __shfl_xor_sync(0xffffffffu, vd, off);
            }
            if (lane == 0 && row < NN) {
                g_asrc[row * HEADS_T + c] = vs;
                g_adst[row * HEADS_T + c] = vd;
            }
        }
    }
}

// ---------------- layers 1&2: one warp per dst, ALL 4 heads ----------------
// Parallel phase: lane = edgeSlot*4 + head (8 edges/chunk). Serial phase:
// shuffle-broadcast (weight, row offset); fixed 8-iter body, LDG.64 fp16
// gathers (256B per edge row across the warp). Invalid tail edges: weight 0,
// source clamped. No-max softmax: logits bounded (~|l|<6) by input scaling.
__global__ void k_agg4(const float* __restrict__ bias) {
    int wip = threadIdx.x >> 5, lane = threadIdx.x & 31;
    int dst = blockIdx.x * 8 + wip;
    if (dst >= NN) return;

    int sub = lane & 3;          // head in parallel phase
    int ej  = lane >> 2;         // edge slot (0..7)
    int myhead = lane >> 3;      // head owning this lane's 4 channels

    float adv = g_adst[dst * HH + sub];
    int p0 = g_rowptr[dst], p1 = g_rowptr[dst + 1];

    float4 acc = make_float4(0.f, 0.f, 0.f, 0.f);
    float ssum = 0.f;
    const __half2* __restrict__ hp = g_hwh;

    for (int b = p0; b < p1; b += 8) {
        int p = b + ej;
        bool valid = (p < p1);
        int src = g_colidx[valid ? p : (p1 - 1)];   // clamp: always a real row
        float t = g_asrc[src * HH + sub] + adv;
        t = (t >= 0.f) ? t : NEG_SLOPE * t;
        float e = valid ? __expf(t) : 0.f;
        int offs = src * (DIM / 2);                 // half2 units
        ssum += e;

        float w[8]; int o[8];
        #pragma unroll
        for (int j = 0; j < 8; j++) {
            w[j] = __shfl_sync(0xffffffffu, e, j * 4 + myhead);
            o[j] = __shfl_sync(0xffffffffu, offs, j * 4);
        }
        #pragma unroll
        for (int j = 0; j < 8; j++) {
            uint2 raw = *reinterpret_cast<const uint2*>(hp + o[j] + lane * 2);
            float2 f0 = __half22float2(*reinterpret_cast<__half2*>(&raw.x));
            float2 f1 = __half22float2(*reinterpret_cast<__half2*>(&raw.y));
            acc.x += w[j] * f0.x; acc.y += w[j] * f0.y;
            acc.z += w[j] * f1.x; acc.w += w[j] * f1.y;
        }
    }
    // ssum per (ej,sub) -> reduce over edge slots (lane bits 2..4)
    ssum += __shfl_xor_sync(0xffffffffu, ssum, 4);
    ssum += __shfl_xor_sync(0xffffffffu, ssum, 8);
    ssum += __shfl_xor_sync(0xffffffffu, ssum, 16);
    float s = __shfl_sync(0xffffffffu, ssum, myhead);
    float inv = 1.f / (s + 1e-16f);

    float4 bb = *reinterpret_cast<const float4*>(bias + lane * 4);
    float4 o4;
    o4.x = acc.x * inv + bb.x;
    o4.y = acc.y * inv + bb.y;
    o4.z = acc.z * inv + bb.z;
    o4.w = acc.w * inv + bb.w;
    o4.x = (o4.x > 0.f) ? o4.x : expm1f(o4.x);   // ELU
    o4.y = (o4.y > 0.f) ? o4.y : expm1f(o4.y);
    o4.z = (o4.z > 0.f) ? o4.z : expm1f(o4.z);
    o4.w = (o4.w > 0.f) ? o4.w : expm1f(o4.w);
    *reinterpret_cast<float4*>(g_h + dst * DIM + lane * 4) = o4;
}

// ---------------- layer 3: warp per dst, single head, write out ----------
__global__ void k_agg1(const float* __restrict__ bias, float* __restrict__ OUT) {
    int wip = threadIdx.x >> 5, lane = threadIdx.x & 31;
    int dst = blockIdx.x * 8 + wip;
    if (dst >= NN) return;

    float adv = g_adst[dst];
    int p0 = g_rowptr[dst], p1 = g_rowptr[dst + 1];
    const __half* __restrict__ hw16 = reinterpret_cast<const __half*>(g_hwh);

    float ssum = 0.f;
    float acc = 0.f;
    for (int b = p0; b < p1; b += 32) {
        int p = b + lane;
        bool valid = (p < p1);
        int src = g_colidx[valid ? p : (p1 - 1)];
        float t = g_asrc[src] + adv;
        t = (t >= 0.f) ? t : NEG_SLOPE * t;
        float e = valid ? __expf(t) : 0.f;
        int offs = src * CC;
        ssum += e;

        int cnt = min(32, p1 - b);
        #pragma unroll
        for (int g = 0; g < 4; g++) {
            if (g * 8 >= cnt) break;            // uniform across warp
            float w[8]; int o[8];
            #pragma unroll
            for (int j = 0; j < 8; j++) {
                w[j] = __shfl_sync(0xffffffffu, e, g * 8 + j);
                o[j] = __shfl_sync(0xffffffffu, offs, g * 8 + j);
            }
            #pragma unroll
            for (int j = 0; j < 8; j++)
                acc += w[j] * __half2float(hw16[o[j] + lane]);
        }
    }
    float s = ssum;
    #pragma unroll
    for (int off = 16; off; off >>= 1)
        s += __shfl_xor_sync(0xffffffffu, s, off);

    OUT[dst * CC + lane] = acc / (s + 1e-16f) + bias[lane];
}

// ---------------- launch ----------------
extern "C" void kernel_launch(void* const* d_in, const int* in_sizes, int n_in,
                              void* d_out, int out_size) {
    const float* x   = (const float*)d_in[0];
    const int*   ei  = (const int*)  d_in[1];
    const float* W1  = (const float*)d_in[2];
    const float* as1 = (const float*)d_in[3];
    const float* ad1 = (const float*)d_in[4];
    const float* b1  = (const float*)d_in[5];
    const float* W2  = (const float*)d_in[6];
    const float* as2 = (const float*)d_in[7];
    const float* ad2 = (const float*)d_in[8];
    const float* b2  = (const float*)d_in[9];
    const float* W3  = (const float*)d_in[10];
    const float* as3 = (const float*)d_in[11];
    const float* ad3 = (const float*)d_in[12];
    const float* b3  = (const float*)d_in[13];
    float* out = (float*)d_out;

    // CSR by destination (self-loops folded into scan)
    void* count_ptr = nullptr;
    cudaGetSymbolAddress(&count_ptr, g_count);
    cudaMemsetAsync(count_ptr, 0, NN * sizeof(int));
    k_count<<<(EE + 255) / 256, 256>>>(ei);
    k_scan<<<1, 1024>>>();
    k_fill<<<(ETOT + 255) / 256, 256>>>(ei);

    const int gemm_blocks = (NN + 31) / 32;
    const int agg_blocks = (NN + 7) / 8;
    const int pack_big = ((DIM / 2) * DIM + 255) / 256;
    const int pack_sm  = ((DIM / 2) * CC + 255) / 256;

    // layer 1
    k_packW<<<pack_big, 256>>>(W1, DIM, DIM);
    k_gemm<DIM, DIM, HH, false><<<gemm_blocks, 128>>>(x, as1, ad1);
    k_agg4<<<agg_blocks, 256>>>(b1);

    // layer 2
    k_packW<<<pack_big, 256>>>(W2, DIM, DIM);
    k_gemm<DIM, DIM, HH, true><<<gemm_blocks, 128>>>(nullptr, as2, ad2);
    k_agg4<<<agg_blocks, 256>>>(b2);

    // layer 3
    k_packW<<<pack_sm, 256>>>(W3, DIM, CC);
    k_gemm<DIM, CC, 1, true><<<gemm_blocks, 128>>>(nullptr, as3, ad3);
    k_agg1<<<agg_blocks, 256>>>(b3, out);
}